// round 15
// baseline (speedup 1.0000x reference)
#include <cuda_runtime.h>
#include <cuda_fp16.h>
#include <math.h>

#define BB 64
#define DD 1024
#define TT 128
#define SS 128
#define EE 512
#define NCTA 128
#define NTHR 512

// ---------------- device scratch (static, no allocations) ----------------
__device__ float g_h0[BB][DD];
__device__ float g_h1[BB][DD];
__device__ float g_c0[BB][DD];
__device__ float g_c1[BB][DD];
__device__ float g_out[BB][DD];
__device__ __half g_out16[BB][DD];
__device__ __half g_h0_16[BB][DD];
__device__ __half g_h1_16[BB][DD];
__device__ __half g_wctx16[BB][DD];
__device__ float g_bias0[4 * DD];
__device__ float g_bias1[4 * DD];
__device__ __half g_Cq16[(size_t)SS * BB * DD];         // (ctx @ W_in) fp16 : [s][b][k]
__device__ __half g_ctx16[(size_t)SS * BB * DD];        // context fp16 copy
__device__ float g_part[8 * 4096 * 64];                 // split-K partials
__device__ float g_pre[(size_t)TT * 4096 * BB];         // emb projection [t][row][b]

// pre-packed fp16 m16n8k16 fragment weights: idx = ((mb*K16 + k16)*32 + lane)
__device__ uint4 g_WfE[256 * 32 * 32];    // lstm0 emb part:  4096 x 512
__device__ uint4 g_Wf0[256 * 128 * 32];   // lstm0 [out|h0]:  4096 x 2048
__device__ uint4 g_Wf1[256 * 128 * 32];   // lstm1 [h0|h1]:   4096 x 2048
__device__ uint4 g_WfO[64 * 128 * 32];    // out  [wctx|h1]:  1024 x 2048
__device__ uint4 g_WfQ[64 * 64 * 32];     // W_in^T:          1024 x 1024

__device__ unsigned g_bar_count;
__device__ volatile unsigned g_bar_epoch;

__device__ __forceinline__ float sigm(float x) { return 1.f / (1.f + __expf(-x)); }

__device__ __forceinline__ unsigned h2u(__half2 h) {
    return *(unsigned*)&h;
}
__device__ __forceinline__ void mma_f16(float* c, const unsigned* a, const unsigned* b) {
    asm volatile(
        "mma.sync.aligned.m16n8k16.row.col.f32.f16.f16.f32 "
        "{%0,%1,%2,%3}, {%4,%5,%6,%7}, {%8,%9}, {%0,%1,%2,%3};"
        : "+f"(c[0]), "+f"(c[1]), "+f"(c[2]), "+f"(c[3])
        : "r"(a[0]), "r"(a[1]), "r"(a[2]), "r"(a[3]), "r"(b[0]), "r"(b[1]));
}

// software grid barrier (128 CTAs, all resident)
__device__ __forceinline__ void grid_barrier() {
    __syncthreads();
    if (threadIdx.x == 0) {
        unsigned e = g_bar_epoch;
        __threadfence();
        unsigned a = atomicAdd(&g_bar_count, 1u);
        if (a == NCTA - 1) {
            g_bar_count = 0;
            __threadfence();
            atomicAdd((unsigned*)&g_bar_epoch, 1u);
        } else {
            while (g_bar_epoch == e) { }
        }
        __threadfence();
    }
    __syncthreads();
}

// ---------------- shared-mem layouts (union restored, round-13 style) -------
struct SmemGemm {
    uint4 A[3][16][2][32];   // 48KB  A fp16 frags, 3-stage
    uint2 Bf[2][8][2][32];   // 8KB   B fp16 frags, 2-stage
};
struct SmemAttn {
    float h1s[DD];           // 4KB
    float wbuf[8][64][8];    // 16KB
};
union SmemU {
    SmemGemm g;
    SmemAttn a;
};

// ---------------- init ----------------
__global__ void init_kernel(const float* __restrict__ h0, const float* __restrict__ c0,
                            const float* __restrict__ io,
                            const float* __restrict__ bih0, const float* __restrict__ bhh0,
                            const float* __restrict__ bih1, const float* __restrict__ bhh1) {
    int i = blockIdx.x * blockDim.x + threadIdx.x;
    if (i < BB * DD) {
        float h0v = h0[i], h1v = h0[BB * DD + i], ov = io[i];
        ((float*)g_h0)[i] = h0v;
        ((float*)g_h1)[i] = h1v;
        ((float*)g_c0)[i] = c0[i];
        ((float*)g_c1)[i] = c0[BB * DD + i];
        ((float*)g_out)[i] = ov;
        ((__half*)g_h0_16)[i] = __float2half(h0v);
        ((__half*)g_h1_16)[i] = __float2half(h1v);
        ((__half*)g_out16)[i] = __float2half(ov);
    }
    if (i < 4 * DD) {
        g_bias0[i] = bih0[i] + bhh0[i];
        g_bias1[i] = bih1[i] + bhh1[i];
    }
}

// ---------------- context -> fp16 copy (one-time) ----------------
__global__ void ctx16_kernel(const float* __restrict__ context) {
    size_t i = (size_t)blockIdx.x * 256 + threadIdx.x;
    if (i < (size_t)SS * BB * DD) g_ctx16[i] = __float2half(context[i]);
}

// ---------------- weight fragment pack (one-time, fp16 m16n8k16 layout) ------
// Destination selected by tag INSIDE device code (host passing of __device__
// symbols silently writes host memory on GB300/ATS — rounds 7/8 bug).
// trans != 0: element (row r, contraction c) read as W1[c*ld1 + r] (W_in^T).
__global__ void pack_kernel(const float* __restrict__ W1, int ld1, int off1,
                            const float* __restrict__ W2, int ld2, int K1w,
                            int K16tot, int mbTot, int which, int trans) {
    uint4* __restrict__ dst = (which == 0) ? g_WfE
                            : (which == 1) ? g_Wf0
                            : (which == 2) ? g_Wf1
                            : (which == 3) ? g_WfO : g_WfQ;
    size_t idx = (size_t)blockIdx.x * 256 + threadIdx.x;
    size_t total = (size_t)mbTot * K16tot * 32;
    if (idx >= total) return;
    int lane = (int)(idx & 31);
    size_t f = idx >> 5;
    int k16 = (int)(f % K16tot);
    int mb = (int)(f / K16tot);
    int g = lane >> 2, t = lane & 3;
    int r0 = mb * 16 + g, r8 = r0 + 8;
    int cA = k16 * 16 + 2 * t;
    int cB = cA + 8;
    #define LDW(r, c) (trans ? W1[(size_t)(c) * ld1 + (r)] \
                     : ((c) < K1w) ? W1[(size_t)(r) * ld1 + off1 + (c)] \
                                   : W2[(size_t)(r) * ld2 + ((c) - K1w)])
    __half2 h0 = __floats2half2_rn(LDW(r0, cA), LDW(r0, cA + 1));
    __half2 h1 = __floats2half2_rn(LDW(r8, cA), LDW(r8, cA + 1));
    __half2 h2 = __floats2half2_rn(LDW(r0, cB), LDW(r0, cB + 1));
    __half2 h3 = __floats2half2_rn(LDW(r8, cB), LDW(r8, cB + 1));
    #undef LDW
    dst[idx] = make_uint4(h2u(h0), h2u(h1), h2u(h2), h2u(h3));
}

// ---------------- pipelined fp16 GEMM core ----------------
__device__ __forceinline__ void issueA(SmemGemm* sm, const uint4* __restrict__ Wf,
                                       int K16tot, int mbG0, int k16Base,
                                       int chunk, int buf, int wid, int lane) {
    int k16c = k16Base + (chunk << 1);
    #pragma unroll
    for (int j = 0; j < 2; j++) {
        int mbk = j * 16 + wid;
        int mbL = mbk >> 1, k16L = mbk & 1;
        const uint4* src = Wf + ((size_t)(mbG0 + mbL) * K16tot + (k16c + k16L)) * 32 + lane;
        unsigned dst = (unsigned)__cvta_generic_to_shared(&sm->A[buf][mbL][k16L][lane]);
        asm volatile("cp.async.cg.shared.global [%0], [%1], 16;" :: "r"(dst), "l"(src));
    }
    asm volatile("cp.async.commit_group;" ::: "memory");
}

// B-fragment load: fp16 activations (xf32=0) or fp32 source (xf32=1, pre_emb).
__device__ __forceinline__ uint2 loadBfrag(const void* const* rp1, const void* const* rp2,
                                           int KX1, int ksBase, int chunk,
                                           int wid, int g, int t4, int xf32) {
    int k0 = ksBase + (chunk << 5);
    int nb = wid >> 1, k16 = wid & 1;
    int b = nb * 8 + g;
    int kbase = k0 + k16 * 16;
    if (xf32) {
        const float* s = (kbase < KX1) ? (const float*)rp1[b] + kbase
                                       : (const float*)rp2[b] + (kbase - KX1);
        float2 v0 = *(const float2*)(s + 2 * t4);
        float2 v1 = *(const float2*)(s + 2 * t4 + 8);
        return make_uint2(h2u(__floats2half2_rn(v0.x, v0.y)),
                          h2u(__floats2half2_rn(v1.x, v1.y)));
    } else {
        const __half* s = (kbase < KX1) ? (const __half*)rp1[b] + kbase
                                        : (const __half*)rp2[b] + (kbase - KX1);
        return make_uint2(*(const unsigned*)(s + 2 * t4),
                          *(const unsigned*)(s + 2 * t4 + 8));
    }
}

// CTA tile 256 rows x 64 batch, 16 warps (8m x 2n), warp tile 32x32, fp16 MMA.
// epi 0: fp32 partials partOut[row*64+b]; epi 1: fp16 Cq at [(sIdx*BB+b)*DD+row].
__device__ __forceinline__ void gemm_async(
    int rowBase, int ksBase, int KS,
    const uint4* __restrict__ Wf, int K16tot,
    const void* const* rp1, const void* const* rp2, int KX1,
    float* __restrict__ partOut, SmemGemm* sm, int epi, int sIdx, int xf32) {
    const int tid = threadIdx.x;
    const int wid = tid >> 5, lane = tid & 31;
    const int g = lane >> 2, t4 = lane & 3;
    const int mb0 = (wid >> 1) << 1;
    const int nb0 = (wid & 1) << 2;
    const int mbG0 = rowBase >> 4;
    const int k16Base = ksBase >> 4;
    const int nChunk = KS >> 5;
    const int nbS = wid >> 1, k16S = wid & 1;

    float acc[2][4][4];
    #pragma unroll
    for (int i = 0; i < 2; i++)
        #pragma unroll
        for (int j = 0; j < 4; j++)
            #pragma unroll
            for (int r = 0; r < 4; r++) acc[i][j][r] = 0.f;

    issueA(sm, Wf, K16tot, mbG0, k16Base, 0, 0, wid, lane);
    if (nChunk > 1) issueA(sm, Wf, K16tot, mbG0, k16Base, 1, 1, wid, lane);
    uint2 pb = loadBfrag(rp1, rp2, KX1, ksBase, 0, wid, g, t4, xf32);

    for (int i = 0; i < nChunk; i++) {
        sm->Bf[i & 1][nbS][k16S][lane] = pb;
        uint2 pbn;
        if (i + 1 < nChunk) {
            pbn = loadBfrag(rp1, rp2, KX1, ksBase, i + 1, wid, g, t4, xf32);
            asm volatile("cp.async.wait_group 1;" ::: "memory");
        } else {
            asm volatile("cp.async.wait_group 0;" ::: "memory");
        }
        __syncthreads();
        const int ab = i % 3;
        #pragma unroll
        for (int k16 = 0; k16 < 2; k16++) {
            uint4 a0 = sm->A[ab][mb0][k16][lane];
            uint4 a1 = sm->A[ab][mb0 + 1][k16][lane];
            #pragma unroll
            for (int nj = 0; nj < 4; nj++) {
                uint2 bb = sm->Bf[i & 1][nb0 + nj][k16][lane];
                mma_f16(acc[0][nj], (const unsigned*)&a0, (const unsigned*)&bb);
                mma_f16(acc[1][nj], (const unsigned*)&a1, (const unsigned*)&bb);
            }
        }
        if (i + 2 < nChunk)
            issueA(sm, Wf, K16tot, mbG0, k16Base, i + 2, (i + 2) % 3, wid, lane);
        if (i + 1 < nChunk) pb = pbn;
    }
    __syncthreads();   // protect smem reuse by the next phase

    if (epi == 0) {
        #pragma unroll
        for (int mi = 0; mi < 2; mi++) {
            int rb = rowBase + (mb0 + mi) * 16 + g;
            #pragma unroll
            for (int nj = 0; nj < 4; nj++) {
                int col = (nb0 + nj) * 8 + 2 * t4;
                *(float2*)&partOut[(size_t)rb * 64 + col]       = make_float2(acc[mi][nj][0], acc[mi][nj][1]);
                *(float2*)&partOut[(size_t)(rb + 8) * 64 + col] = make_float2(acc[mi][nj][2], acc[mi][nj][3]);
            }
        }
    } else {
        #pragma unroll
        for (int mi = 0; mi < 2; mi++) {
            int rb = rowBase + (mb0 + mi) * 16 + g;
            #pragma unroll
            for (int nj = 0; nj < 4; nj++) {
                int col = (nb0 + nj) * 8 + 2 * t4;
                g_Cq16[((size_t)sIdx * BB + col)     * DD + rb]     = __float2half(acc[mi][nj][0]);
                g_Cq16[((size_t)sIdx * BB + col + 1) * DD + rb]     = __float2half(acc[mi][nj][1]);
                g_Cq16[((size_t)sIdx * BB + col)     * DD + rb + 8] = __float2half(acc[mi][nj][2]);
                g_Cq16[((size_t)sIdx * BB + col + 1) * DD + rb + 8] = __float2half(acc[mi][nj][3]);
            }
        }
    }
}

// ---------------- Cq precompute (one-time, tensor cores) ----------------
// Cq[s][b][k] = sum_d context[s][b][d] * Win[d][k]   (WfQ holds Win^T)
__global__ __launch_bounds__(NTHR, 1) void cq16_kernel() {
    extern __shared__ char dynsm[];
    SmemGemm* sm = (SmemGemm*)dynsm;
    __shared__ const void* rp1[64];
    const int s = blockIdx.y;
    if (threadIdx.x < 64)
        rp1[threadIdx.x] = g_ctx16 + (size_t)(s * BB + threadIdx.x) * DD;
    __syncthreads();
    gemm_async(blockIdx.x * 256, 0, DD, g_WfQ, 64,
               rp1, rp1, 1 << 30, nullptr, sm, 1, s, 0);
}

// ---------------- emb projection (one-time, tensor cores) ----------------
__global__ __launch_bounds__(NTHR, 1) void pre_emb_kernel(
    const int* __restrict__ input, const float* __restrict__ word_lut) {
    extern __shared__ char dynsm[];
    SmemGemm* sm = (SmemGemm*)dynsm;
    __shared__ const void* rp1[64];
    const int t = blockIdx.y;
    if (threadIdx.x < 64) {
        int tok = input[threadIdx.x * TT + t];
        rp1[threadIdx.x] = word_lut + (size_t)tok * EE;
    }
    __syncthreads();
    gemm_async(blockIdx.x * 256, 0, EE, g_WfE, EE / 16,
               rp1, rp1, 1 << 30, g_pre + (size_t)t * 4096 * 64, sm, 0, 0, 1);
}

// ---------------- step phases ----------------
__device__ __forceinline__ void cell_phase(int layer, int t) {
    int e = blockIdx.x * NTHR + threadIdx.x;    // 65536 = BB*DD
    int b = e & 63, d = e >> 6;
    const float* bias = layer ? g_bias1 : g_bias0;
    float gg[4];
    #pragma unroll
    for (int gate = 0; gate < 4; gate++) {
        int row = gate * DD + d;
        float s = bias[row];
        if (layer == 0) s += g_pre[((size_t)t * 4096 + row) * 64 + b];
        #pragma unroll
        for (int ks = 0; ks < 8; ks++)
            s += g_part[((size_t)ks * 4096 + row) * 64 + b];
        gg[gate] = s;
    }
    if (layer) {
        float cn = sigm(gg[1]) * g_c1[b][d] + sigm(gg[0]) * tanhf(gg[2]);
        float hn = sigm(gg[3]) * tanhf(cn);
        g_c1[b][d] = cn;
        g_h1[b][d] = hn;
        g_h1_16[b][d] = __float2half(hn);
    } else {
        float cn = sigm(gg[1]) * g_c0[b][d] + sigm(gg[0]) * tanhf(gg[2]);
        float hn = sigm(gg[3]) * tanhf(cn);
        g_c0[b][d] = cn;
        g_h0[b][d] = hn;
        g_h0_16[b][d] = __float2half(hn);
    }
}

__device__ __forceinline__ void attn_phase(
    int t, float* __restrict__ attns,
    SmemAttn* sm, float* sc, float* red) {
    const int tid = threadIdx.x;
    const int b = blockIdx.x >> 1;
    const int half = blockIdx.x & 1;
    const int lane = tid & 31, warp = tid >> 5;

    for (int i = tid; i < DD; i += NTHR) sm->h1s[i] = g_h1[b][i];
    __syncthreads();

    // scores[s] = Cq16[s,b,:] . h1
    #pragma unroll
    for (int i = 0; i < 8; i++) {
        int s = warp + 16 * i;
        const uint4* cp = (const uint4*)(g_Cq16 + (size_t)(s * BB + b) * DD);
        float p = 0.f;
        #pragma unroll
        for (int jj = 0; jj < 4; jj++) {
            int u = lane + jj * 32;
            uint4 q = cp[u];
            const __half2* hh = (const __half2*)&q;
            float2 f0 = __half22float2(hh[0]);
            float2 f1 = __half22float2(hh[1]);
            float2 f2 = __half22float2(hh[2]);
            float2 f3 = __half22float2(hh[3]);
            int base = u * 8;
            p += f0.x * sm->h1s[base]     + f0.y * sm->h1s[base + 1] +
                 f1.x * sm->h1s[base + 2] + f1.y * sm->h1s[base + 3] +
                 f2.x * sm->h1s[base + 4] + f2.y * sm->h1s[base + 5] +
                 f3.x * sm->h1s[base + 6] + f3.y * sm->h1s[base + 7];
        }
        #pragma unroll
        for (int off = 16; off; off >>= 1) p += __shfl_xor_sync(~0u, p, off);
        if (lane == 0) sc[s] = p;
    }
    __syncthreads();

    float v = (tid < 128) ? sc[tid] : -1e30f;
    float m = v;
    #pragma unroll
    for (int off = 16; off; off >>= 1) m = fmaxf(m, __shfl_xor_sync(~0u, m, off));
    if (tid < 128 && lane == 0) red[warp] = m;
    __syncthreads();
    m = fmaxf(fmaxf(red[0], red[1]), fmaxf(red[2], red[3]));
    float ex = (tid < 128) ? __expf(v - m) : 0.f;
    float ssum = ex;
    #pragma unroll
    for (int off = 16; off; off >>= 1) ssum += __shfl_xor_sync(~0u, ssum, off);
    if (tid < 128 && lane == 0) red[4 + warp] = ssum;
    __syncthreads();
    ssum = red[4] + red[5] + red[6] + red[7];
    if (tid < 128) {
        float a = ex / ssum;
        sc[tid] = a;
        if (half == 0) attns[((size_t)b * TT + t) * SS + tid] = a;
    }
    __syncthreads();

    // wctx[d] = sum_s a[s] * ctx16[s,b,d]; 8 s-groups x 64 d8-columns
    const int g8 = tid >> 6, j = tid & 63;
    const int d8 = half * 512 + j * 8;
    float a8[8];
    #pragma unroll
    for (int q = 0; q < 8; q++) a8[q] = 0.f;
    for (int s = g8 * 16; s < g8 * 16 + 16; s++) {
        float as = sc[s];
        uint4 vv = *(const uint4*)(g_ctx16 + (size_t)(s * BB + b) * DD + d8);
        const __half2* hh = (const __half2*)&vv;
        float2 f0 = __half22float2(hh[0]);
        float2 f1 = __half22float2(hh[1]);
        float2 f2 = __half22float2(hh[2]);
        float2 f3 = __half22float2(hh[3]);
        a8[0] += as * f0.x; a8[1] += as * f0.y;
        a8[2] += as * f1.x; a8[3] += as * f1.y;
        a8[4] += as * f2.x; a8[5] += as * f2.y;
        a8[6] += as * f3.x; a8[7] += as * f3.y;
    }
    #pragma unroll
    for (int q = 0; q < 8; q++) sm->wbuf[g8][j][q] = a8[q];
    __syncthreads();
    if (g8 == 0) {
        float o[8];
        #pragma unroll
        for (int q = 0; q < 8; q++) o[q] = 0.f;
        #pragma unroll
        for (int gg = 0; gg < 8; gg++)
            #pragma unroll
            for (int q = 0; q < 8; q++) o[q] += sm->wbuf[gg][j][q];
        __half2 p0 = __floats2half2_rn(o[0], o[1]);
        __half2 p1 = __floats2half2_rn(o[2], o[3]);
        __half2 p2 = __floats2half2_rn(o[4], o[5]);
        __half2 p3 = __floats2half2_rn(o[6], o[7]);
        *(uint4*)&g_wctx16[b][d8] = make_uint4(h2u(p0), h2u(p1), h2u(p2), h2u(p3));
    }
    __syncthreads();
}

__device__ __forceinline__ void outred_phase(int t, float* __restrict__ outs) {
    int e = blockIdx.x * NTHR + threadIdx.x;
    int b = e & 63, d = e >> 6;
    float s = 0.f;
    #pragma unroll
    for (int ks = 0; ks < 32; ks++)
        s += g_part[((size_t)ks * 1024 + d) * 64 + b];
    float v = tanhf(s);
    g_out[b][d] = v;
    g_out16[b][d] = __float2half(v);
    outs[((size_t)b * TT + t) * DD + d] = v;
}

// ---------------- persistent kernel: all 128 timesteps ----------------
__global__ __launch_bounds__(NTHR, 1) void main_kernel(
    float* __restrict__ outs, float* __restrict__ attns) {
    extern __shared__ char dynsm[];
    SmemU* sm = (SmemU*)dynsm;
    __shared__ const void* rp1[64];
    __shared__ const void* rp2[64];
    __shared__ float sc[SS];
    __shared__ float red[8];
    const int tid = threadIdx.x;
    const int bid = blockIdx.x;

    const int rb0 = (bid & 15) * 256, ks0 = (bid >> 4) * 256;  // lstm tiles
    const int rbO = (bid & 3) * 256,  ksO = (bid >> 2) * 64;   // out tiles

    for (int t = 0; t < TT; t++) {
        // lstm0 gates: x = [out16 | h0_16], K=2048, 16 rowtiles x 8 ksplit
        if (tid < 64) { rp1[tid] = &g_out16[tid][0]; rp2[tid] = &g_h0_16[tid][0]; }
        __syncthreads();
        gemm_async(rb0, ks0, 256, g_Wf0, 128, rp1, rp2, DD,
                   g_part + (size_t)(bid >> 4) * 4096 * 64, &sm->g, 0, 0, 0);
        grid_barrier();
        cell_phase(0, t);
        grid_barrier();
        // lstm1 gates: x = [h0_16 | h1_16]
        if (tid < 64) { rp1[tid] = &g_h0_16[tid][0]; rp2[tid] = &g_h1_16[tid][0]; }
        __syncthreads();
        gemm_async(rb0, ks0, 256, g_Wf1, 128, rp1, rp2, DD,
                   g_part + (size_t)(bid >> 4) * 4096 * 64, &sm->g, 0, 0, 0);
        grid_barrier();
        cell_phase(1, t);
        grid_barrier();
        attn_phase(t, attns, &sm->a, sc, red);
        grid_barrier();
        // out gemm: x = [wctx16 | h1_16], 4 rowtiles x 32 ksplit
        if (tid < 64) { rp1[tid] = &g_wctx16[tid][0]; rp2[tid] = &g_h1_16[tid][0]; }
        __syncthreads();
        gemm_async(rbO, ksO, 64, g_WfO, 128, rp1, rp2, DD,
                   g_part + (size_t)(bid >> 2) * 1024 * 64, &sm->g, 0, 0, 0);
        grid_barrier();
        outred_phase(t, outs);
        grid_barrier();     // next step's lstm0 reads g_out16
    }
}

// ---------------- final ----------------
__global__ void final_kernel(float* __restrict__ hout, float* __restrict__ cout) {
    int i = blockIdx.x * blockDim.x + threadIdx.x;
    if (i < BB * DD) {
        hout[i]           = ((float*)g_h0)[i];
        hout[BB * DD + i] = ((float*)g_h1)[i];
        cout[i]           = ((float*)g_c0)[i];
        cout[BB * DD + i] = ((float*)g_c1)[i];
    }
}

// ---------------- launch ----------------
extern "C" void kernel_launch(void* const* d_in, const int* in_sizes, int n_in,
                              void* d_out, int out_size) {
    const int*   input    = (const int*)d_in[0];
    const float* h0       = (const float*)d_in[2];
    const float* c0       = (const float*)d_in[3];
    const float* context  = (const float*)d_in[4];
    const float* init_out = (const float*)d_in[5];
    const float* word_lut = (const float*)d_in[6];
    const float* Wih0 = (const float*)d_in[7];
    const float* Whh0 = (const float*)d_in[8];
    const float* bih0 = (const float*)d_in[9];
    const float* bhh0 = (const float*)d_in[10];
    const float* Wih1 = (const float*)d_in[11];
    const float* Whh1 = (const float*)d_in[12];
    const float* bih1 = (const float*)d_in[13];
    const float* bhh1 = (const float*)d_in[14];
    const float* Win  = (const float*)d_in[15];
    const float* Wout = (const float*)d_in[16];

    float* out   = (float*)d_out;
    float* outs  = out;                           // [B,T,D]
    float* hout  = out + (size_t)BB * TT * DD;    // [2,B,D]
    float* cout  = hout + 2 * BB * DD;            // [2,B,D]
    float* attns = cout + 2 * BB * DD;            // [B,T,S]

    cudaFuncSetAttribute(main_kernel, cudaFuncAttributeMaxDynamicSharedMemorySize,
                         (int)sizeof(SmemU));
    cudaFuncSetAttribute(pre_emb_kernel, cudaFuncAttributeMaxDynamicSharedMemorySize,
                         (int)sizeof(SmemGemm));
    cudaFuncSetAttribute(cq16_kernel, cudaFuncAttributeMaxDynamicSharedMemorySize,
                         (int)sizeof(SmemGemm));

    init_kernel<<<256, 256>>>(h0, c0, init_out, bih0, bhh0, bih1, bhh1);
    ctx16_kernel<<<32768, 256>>>(context);
    // packs: (W1, ld1, off1, W2, ld2, K1w, K16tot, mbTot, which, trans)
    pack_kernel<<<1024, 256>>>(Wih0, 1536, 0,   Wih0, 1536, 512,  32,  256, 0, 0);
    pack_kernel<<<4096, 256>>>(Wih0, 1536, 512, Whh0, 1024, 1024, 128, 256, 1, 0);
    pack_kernel<<<4096, 256>>>(Wih1, 1024, 0,   Whh1, 1024, 1024, 128, 256, 2, 0);
    pack_kernel<<<1024, 256>>>(Wout, 2048, 0,   Wout, 2048, 2048, 128, 64,  3, 0);
    pack_kernel<<<512, 256>>>(Win,  1024, 0,   Win,  1024, 1024, 64,  64,  4, 1);
    cq16_kernel<<<dim3(4, 128), NTHR, sizeof(SmemGemm)>>>();
    pre_emb_kernel<<<dim3(16, 128), NTHR, sizeof(SmemGemm)>>>(input, word_lut);
    main_kernel<<<NCTA, NTHR, sizeof(SmemU)>>>(outs, attns);
    final_kernel<<<256, 256>>>(hout, cout);
}

// round 16
// speedup vs baseline: 1.0424x; 1.0424x over previous
#include <cuda_runtime.h>
#include <cuda_fp16.h>
#include <math.h>

#define BB 64
#define DD 1024
#define TT 128
#define SS 128
#define EE 512
#define NCTA 128
#define NTHR 512

// ---------------- device scratch (static, no allocations) ----------------
__device__ float g_h0[BB][DD];
__device__ float g_h1[BB][DD];
__device__ float g_c0[BB][DD];
__device__ float g_c1[BB][DD];
__device__ float g_out[BB][DD];
__device__ float g_wctx[BB][DD];
__device__ float g_bias0[4 * DD];
__device__ float g_bias1[4 * DD];
__device__ __half g_Cq16[(size_t)SS * BB * DD];         // (ctx @ W_in) fp16 : [s][b][k]
__device__ __half g_ctx16[(size_t)SS * BB * DD];        // context fp16 copy
__device__ __half g_part16[8 * 4096 * 64];              // split-K partials (fp16, 4MB)
__device__ float g_pre[(size_t)TT * 4096 * BB];         // emb projection [t][row][b] (fp32)

// pre-packed fp16 m16n8k16 fragment weights: idx = ((mb*K16 + k16)*32 + lane)
__device__ uint4 g_WfE[256 * 32 * 32];    // lstm0 emb part:  4096 x 512
__device__ uint4 g_Wf0[256 * 128 * 32];   // lstm0 [out|h0]:  4096 x 2048
__device__ uint4 g_Wf1[256 * 128 * 32];   // lstm1 [h0|h1]:   4096 x 2048
__device__ uint4 g_WfO[64 * 128 * 32];    // out  [wctx|h1]:  1024 x 2048
__device__ uint4 g_WfQ[64 * 64 * 32];     // W_in^T:          1024 x 1024

__device__ unsigned g_bar_count;
__device__ volatile unsigned g_bar_epoch;

__device__ __forceinline__ float sigm(float x) { return 1.f / (1.f + __expf(-x)); }

__device__ __forceinline__ unsigned h2u(__half2 h) {
    return *(unsigned*)&h;
}
__device__ __forceinline__ void mma_f16(float* c, const unsigned* a, const unsigned* b) {
    asm volatile(
        "mma.sync.aligned.m16n8k16.row.col.f32.f16.f16.f32 "
        "{%0,%1,%2,%3}, {%4,%5,%6,%7}, {%8,%9}, {%0,%1,%2,%3};"
        : "+f"(c[0]), "+f"(c[1]), "+f"(c[2]), "+f"(c[3])
        : "r"(a[0]), "r"(a[1]), "r"(a[2]), "r"(a[3]), "r"(b[0]), "r"(b[1]));
}

// software grid barrier (128 CTAs, all resident)
__device__ __forceinline__ void grid_barrier() {
    __syncthreads();
    if (threadIdx.x == 0) {
        unsigned e = g_bar_epoch;
        __threadfence();
        unsigned a = atomicAdd(&g_bar_count, 1u);
        if (a == NCTA - 1) {
            g_bar_count = 0;
            __threadfence();
            atomicAdd((unsigned*)&g_bar_epoch, 1u);
        } else {
            while (g_bar_epoch == e) { }
        }
        __threadfence();
    }
    __syncthreads();
}

// ---------------- shared-mem layouts (union, round-13 structure) ------------
struct SmemGemm {
    uint4 A[3][16][2][32];   // 48KB  A fp16 frags, 3-stage
    uint2 Bf[2][8][2][32];   // 8KB   B fp16 frags, 2-stage
};
struct SmemAttn {
    float h1s[DD];           // 4KB
    float4 wbuf[4][128];     // 8KB
};
union SmemU {
    SmemGemm g;
    SmemAttn a;
};

// ---------------- init ----------------
__global__ void init_kernel(const float* __restrict__ h0, const float* __restrict__ c0,
                            const float* __restrict__ io,
                            const float* __restrict__ bih0, const float* __restrict__ bhh0,
                            const float* __restrict__ bih1, const float* __restrict__ bhh1) {
    int i = blockIdx.x * blockDim.x + threadIdx.x;
    if (i < BB * DD) {
        ((float*)g_h0)[i] = h0[i];
        ((float*)g_h1)[i] = h0[BB * DD + i];
        ((float*)g_c0)[i] = c0[i];
        ((float*)g_c1)[i] = c0[BB * DD + i];
        ((float*)g_out)[i] = io[i];
    }
    if (i < 4 * DD) {
        g_bias0[i] = bih0[i] + bhh0[i];
        g_bias1[i] = bih1[i] + bhh1[i];
    }
}

// ---------------- context -> fp16 copy (one-time) ----------------
__global__ void ctx16_kernel(const float* __restrict__ context) {
    size_t i = (size_t)blockIdx.x * 256 + threadIdx.x;
    if (i < (size_t)SS * BB * DD) g_ctx16[i] = __float2half(context[i]);
}

// ---------------- weight fragment pack (one-time, fp16 m16n8k16 layout) ------
// Destination selected by tag INSIDE device code (host passing of __device__
// symbols silently writes host memory on GB300/ATS — rounds 7/8 bug).
// trans != 0: element (row r, contraction c) read as W1[c*ld1 + r] (W_in^T).
__global__ void pack_kernel(const float* __restrict__ W1, int ld1, int off1,
                            const float* __restrict__ W2, int ld2, int K1w,
                            int K16tot, int mbTot, int which, int trans) {
    uint4* __restrict__ dst = (which == 0) ? g_WfE
                            : (which == 1) ? g_Wf0
                            : (which == 2) ? g_Wf1
                            : (which == 3) ? g_WfO : g_WfQ;
    size_t idx = (size_t)blockIdx.x * 256 + threadIdx.x;
    size_t total = (size_t)mbTot * K16tot * 32;
    if (idx >= total) return;
    int lane = (int)(idx & 31);
    size_t f = idx >> 5;
    int k16 = (int)(f % K16tot);
    int mb = (int)(f / K16tot);
    int g = lane >> 2, t = lane & 3;
    int r0 = mb * 16 + g, r8 = r0 + 8;
    int cA = k16 * 16 + 2 * t;
    int cB = cA + 8;
    #define LDW(r, c) (trans ? W1[(size_t)(c) * ld1 + (r)] \
                     : ((c) < K1w) ? W1[(size_t)(r) * ld1 + off1 + (c)] \
                                   : W2[(size_t)(r) * ld2 + ((c) - K1w)])
    __half2 h0 = __floats2half2_rn(LDW(r0, cA), LDW(r0, cA + 1));
    __half2 h1 = __floats2half2_rn(LDW(r8, cA), LDW(r8, cA + 1));
    __half2 h2 = __floats2half2_rn(LDW(r0, cB), LDW(r0, cB + 1));
    __half2 h3 = __floats2half2_rn(LDW(r8, cB), LDW(r8, cB + 1));
    #undef LDW
    dst[idx] = make_uint4(h2u(h0), h2u(h1), h2u(h2), h2u(h3));
}

// ---------------- pipelined fp16 GEMM core ----------------
__device__ __forceinline__ void issueA(SmemGemm* sm, const uint4* __restrict__ Wf,
                                       int K16tot, int mbG0, int k16Base,
                                       int chunk, int buf, int wid, int lane) {
    int k16c = k16Base + (chunk << 1);
    #pragma unroll
    for (int j = 0; j < 2; j++) {
        int mbk = j * 16 + wid;
        int mbL = mbk >> 1, k16L = mbk & 1;
        const uint4* src = Wf + ((size_t)(mbG0 + mbL) * K16tot + (k16c + k16L)) * 32 + lane;
        unsigned dst = (unsigned)__cvta_generic_to_shared(&sm->A[buf][mbL][k16L][lane]);
        asm volatile("cp.async.cg.shared.global [%0], [%1], 16;" :: "r"(dst), "l"(src));
    }
    asm volatile("cp.async.commit_group;" ::: "memory");
}

// B-fragment load (fp32 sources, cvt at staging — round-13 path)
__device__ __forceinline__ void loadB(const float* const* rp1, const float* const* rp2,
                                      int KX1, int ksBase, int chunk,
                                      int wid, int g, int t4, float pbv[4]) {
    int k0 = ksBase + (chunk << 5);
    int nb = wid >> 1, k16 = wid & 1;
    int b = nb * 8 + g;
    int kbase = k0 + k16 * 16;
    const float* s = (kbase < KX1) ? rp1[b] + kbase : rp2[b] + (kbase - KX1);
    float2 v0 = *(const float2*)(s + 2 * t4);
    float2 v1 = *(const float2*)(s + 2 * t4 + 8);
    pbv[0] = v0.x; pbv[1] = v0.y; pbv[2] = v1.x; pbv[3] = v1.y;
}

// CTA tile 256 rows x 64 batch, 16 warps (8m x 2n), warp tile 32x32, fp16 MMA.
// epi 0: fp16 partials at ((__half*)partOut)[row*64+b]
// epi 1: fp16 Cq at g_Cq16[(sIdx*BB+b)*DD + row]
// epi 2: fp32 partials at ((float*)partOut)[row*64+b]   (pre_emb)
__device__ __forceinline__ void gemm_async(
    int rowBase, int ksBase, int KS,
    const uint4* __restrict__ Wf, int K16tot,
    const float* const* rp1, const float* const* rp2, int KX1,
    void* __restrict__ partOut, SmemGemm* sm, int epi, int sIdx) {
    const int tid = threadIdx.x;
    const int wid = tid >> 5, lane = tid & 31;
    const int g = lane >> 2, t4 = lane & 3;
    const int mb0 = (wid >> 1) << 1;
    const int nb0 = (wid & 1) << 2;
    const int mbG0 = rowBase >> 4;
    const int k16Base = ksBase >> 4;
    const int nChunk = KS >> 5;
    const int nbS = wid >> 1, k16S = wid & 1;

    float acc[2][4][4];
    #pragma unroll
    for (int i = 0; i < 2; i++)
        #pragma unroll
        for (int j = 0; j < 4; j++)
            #pragma unroll
            for (int r = 0; r < 4; r++) acc[i][j][r] = 0.f;

    issueA(sm, Wf, K16tot, mbG0, k16Base, 0, 0, wid, lane);
    if (nChunk > 1) issueA(sm, Wf, K16tot, mbG0, k16Base, 1, 1, wid, lane);
    float pb[4];
    loadB(rp1, rp2, KX1, ksBase, 0, wid, g, t4, pb);

    for (int i = 0; i < nChunk; i++) {
        {
            __half2 hA = __floats2half2_rn(pb[0], pb[1]);
            __half2 hB = __floats2half2_rn(pb[2], pb[3]);
            sm->Bf[i & 1][nbS][k16S][lane] = make_uint2(h2u(hA), h2u(hB));
        }
        float pbn[4];
        if (i + 1 < nChunk) {
            loadB(rp1, rp2, KX1, ksBase, i + 1, wid, g, t4, pbn);
            asm volatile("cp.async.wait_group 1;" ::: "memory");
        } else {
            asm volatile("cp.async.wait_group 0;" ::: "memory");
        }
        __syncthreads();
        const int ab = i % 3;
        #pragma unroll
        for (int k16 = 0; k16 < 2; k16++) {
            uint4 a0 = sm->A[ab][mb0][k16][lane];
            uint4 a1 = sm->A[ab][mb0 + 1][k16][lane];
            #pragma unroll
            for (int nj = 0; nj < 4; nj++) {
                uint2 bb = sm->Bf[i & 1][nb0 + nj][k16][lane];
                mma_f16(acc[0][nj], (const unsigned*)&a0, (const unsigned*)&bb);
                mma_f16(acc[1][nj], (const unsigned*)&a1, (const unsigned*)&bb);
            }
        }
        if (i + 2 < nChunk)
            issueA(sm, Wf, K16tot, mbG0, k16Base, i + 2, (i + 2) % 3, wid, lane);
        if (i + 1 < nChunk) {
            pb[0] = pbn[0]; pb[1] = pbn[1]; pb[2] = pbn[2]; pb[3] = pbn[3];
        }
    }
    __syncthreads();   // protect smem reuse by the next phase

    if (epi == 0) {
        __half* po = (__half*)partOut;
        #pragma unroll
        for (int mi = 0; mi < 2; mi++) {
            int rb = rowBase + (mb0 + mi) * 16 + g;
            #pragma unroll
            for (int nj = 0; nj < 4; nj++) {
                int col = (nb0 + nj) * 8 + 2 * t4;
                *(unsigned*)&po[(size_t)rb * 64 + col] =
                    h2u(__floats2half2_rn(acc[mi][nj][0], acc[mi][nj][1]));
                *(unsigned*)&po[(size_t)(rb + 8) * 64 + col] =
                    h2u(__floats2half2_rn(acc[mi][nj][2], acc[mi][nj][3]));
            }
        }
    } else if (epi == 2) {
        float* po = (float*)partOut;
        #pragma unroll
        for (int mi = 0; mi < 2; mi++) {
            int rb = rowBase + (mb0 + mi) * 16 + g;
            #pragma unroll
            for (int nj = 0; nj < 4; nj++) {
                int col = (nb0 + nj) * 8 + 2 * t4;
                *(float2*)&po[(size_t)rb * 64 + col]       = make_float2(acc[mi][nj][0], acc[mi][nj][1]);
                *(float2*)&po[(size_t)(rb + 8) * 64 + col] = make_float2(acc[mi][nj][2], acc[mi][nj][3]);
            }
        }
    } else {
        #pragma unroll
        for (int mi = 0; mi < 2; mi++) {
            int rb = rowBase + (mb0 + mi) * 16 + g;
            #pragma unroll
            for (int nj = 0; nj < 4; nj++) {
                int col = (nb0 + nj) * 8 + 2 * t4;
                g_Cq16[((size_t)sIdx * BB + col)     * DD + rb]     = __float2half(acc[mi][nj][0]);
                g_Cq16[((size_t)sIdx * BB + col + 1) * DD + rb]     = __float2half(acc[mi][nj][1]);
                g_Cq16[((size_t)sIdx * BB + col)     * DD + rb + 8] = __float2half(acc[mi][nj][2]);
                g_Cq16[((size_t)sIdx * BB + col + 1) * DD + rb + 8] = __float2half(acc[mi][nj][3]);
            }
        }
    }
}

// ---------------- Cq precompute (one-time, tensor cores) ----------------
// Cq[s][b][k] = sum_d context[s][b][d] * Win[d][k]   (WfQ holds Win^T)
__global__ __launch_bounds__(NTHR, 1) void cq16_kernel(const float* __restrict__ context) {
    extern __shared__ char dynsm[];
    SmemGemm* sm = (SmemGemm*)dynsm;
    __shared__ const float* rp1[64];
    const int s = blockIdx.y;
    if (threadIdx.x < 64)
        rp1[threadIdx.x] = context + (size_t)(s * BB + threadIdx.x) * DD;
    __syncthreads();
    gemm_async(blockIdx.x * 256, 0, DD, g_WfQ, 64,
               rp1, rp1, 1 << 30, nullptr, sm, 1, s);
}

// ---------------- emb projection (one-time, tensor cores, fp32 out) ---------
__global__ __launch_bounds__(NTHR, 1) void pre_emb_kernel(
    const int* __restrict__ input, const float* __restrict__ word_lut) {
    extern __shared__ char dynsm[];
    SmemGemm* sm = (SmemGemm*)dynsm;
    __shared__ const float* rp1[64];
    const int t = blockIdx.y;
    if (threadIdx.x < 64) {
        int tok = input[threadIdx.x * TT + t];
        rp1[threadIdx.x] = word_lut + (size_t)tok * EE;
    }
    __syncthreads();
    gemm_async(blockIdx.x * 256, 0, EE, g_WfE, EE / 16,
               rp1, rp1, 1 << 30, g_pre + (size_t)t * 4096 * 64, sm, 2, 0);
}

// ---------------- step phases ----------------
__device__ __forceinline__ void cell_phase(int layer, int t) {
    int e = blockIdx.x * NTHR + threadIdx.x;    // 65536 = BB*DD
    int b = e & 63, d = e >> 6;
    const float* bias = layer ? g_bias1 : g_bias0;
    float gg[4];
    #pragma unroll
    for (int gate = 0; gate < 4; gate++) {
        int row = gate * DD + d;
        float s = bias[row];
        if (layer == 0) s += g_pre[((size_t)t * 4096 + row) * 64 + b];
        #pragma unroll
        for (int ks = 0; ks < 8; ks++)
            s += __half2float(g_part16[((size_t)ks * 4096 + row) * 64 + b]);
        gg[gate] = s;
    }
    if (layer) {
        float cn = sigm(gg[1]) * g_c1[b][d] + sigm(gg[0]) * tanhf(gg[2]);
        g_c1[b][d] = cn;
        g_h1[b][d] = sigm(gg[3]) * tanhf(cn);
    } else {
        float cn = sigm(gg[1]) * g_c0[b][d] + sigm(gg[0]) * tanhf(gg[2]);
        g_c0[b][d] = cn;
        g_h0[b][d] = sigm(gg[3]) * tanhf(cn);
    }
}

__device__ __forceinline__ void attn_phase(
    int t, float* __restrict__ attns,
    SmemAttn* sm, float* sc, float* red) {
    const int tid = threadIdx.x;
    const int b = blockIdx.x >> 1;
    const int half = blockIdx.x & 1;
    const int lane = tid & 31, warp = tid >> 5;

    for (int i = tid; i < DD; i += NTHR) sm->h1s[i] = g_h1[b][i];
    __syncthreads();

    // scores[s] = Cq16[s,b,:] . h1
    #pragma unroll
    for (int i = 0; i < 8; i++) {
        int s = warp + 16 * i;
        const uint4* cp = (const uint4*)(g_Cq16 + (size_t)(s * BB + b) * DD);
        float p = 0.f;
        #pragma unroll
        for (int jj = 0; jj < 4; jj++) {
            int u = lane + jj * 32;
            uint4 q = cp[u];
            const __half2* hh = (const __half2*)&q;
            float2 f0 = __half22float2(hh[0]);
            float2 f1 = __half22float2(hh[1]);
            float2 f2 = __half22float2(hh[2]);
            float2 f3 = __half22float2(hh[3]);
            int base = u * 8;
            p += f0.x * sm->h1s[base]     + f0.y * sm->h1s[base + 1] +
                 f1.x * sm->h1s[base + 2] + f1.y * sm->h1s[base + 3] +
                 f2.x * sm->h1s[base + 4] + f2.y * sm->h1s[base + 5] +
                 f3.x * sm->h1s[base + 6] + f3.y * sm->h1s[base + 7];
        }
        #pragma unroll
        for (int off = 16; off; off >>= 1) p += __shfl_xor_sync(~0u, p, off);
        if (lane == 0) sc[s] = p;
    }
    __syncthreads();

    float v = (tid < 128) ? sc[tid] : -1e30f;
    float m = v;
    #pragma unroll
    for (int off = 16; off; off >>= 1) m = fmaxf(m, __shfl_xor_sync(~0u, m, off));
    if (tid < 128 && lane == 0) red[warp] = m;
    __syncthreads();
    m = fmaxf(fmaxf(red[0], red[1]), fmaxf(red[2], red[3]));
    float ex = (tid < 128) ? __expf(v - m) : 0.f;
    float ssum = ex;
    #pragma unroll
    for (int off = 16; off; off >>= 1) ssum += __shfl_xor_sync(~0u, ssum, off);
    if (tid < 128 && lane == 0) red[4 + warp] = ssum;
    __syncthreads();
    ssum = red[4] + red[5] + red[6] + red[7];
    if (tid < 128) {
        float a = ex / ssum;
        sc[tid] = a;
        if (half == 0) attns[((size_t)b * TT + t) * SS + tid] = a;
    }
    __syncthreads();

    // wctx[d] = sum_s a[s] * ctx16[s,b,d]; 4 s-groups x 128 d4-columns
    const int g = tid >> 7, j = tid & 127;
    const int d4 = half * 512 + j * 4;
    float4 a4 = make_float4(0.f, 0.f, 0.f, 0.f);
    for (int s = g * 32; s < g * 32 + 32; s++) {
        float as = sc[s];
        uint2 vv = *(const uint2*)(g_ctx16 + (size_t)(s * BB + b) * DD + d4);
        const __half2* hh = (const __half2*)&vv;
        float2 f0 = __half22float2(hh[0]);
        float2 f1 = __half22float2(hh[1]);
        a4.x += as * f0.x; a4.y += as * f0.y;
        a4.z += as * f1.x; a4.w += as * f1.y;
    }
    sm->wbuf[g][j] = a4;
    __syncthreads();
    if (g == 0) {
        float4 r0 = sm->wbuf[0][j], r1 = sm->wbuf[1][j], r2 = sm->wbuf[2][j], r3 = sm->wbuf[3][j];
        float4 o = make_float4(r0.x + r1.x + r2.x + r3.x, r0.y + r1.y + r2.y + r3.y,
                               r0.z + r1.z + r2.z + r3.z, r0.w + r1.w + r2.w + r3.w);
        *(float4*)&g_wctx[b][d4] = o;
    }
    __syncthreads();
}

__device__ __forceinline__ void outred_phase(int t, float* __restrict__ outs) {
    int e = blockIdx.x * NTHR + threadIdx.x;
    int b = e & 63, d = e >> 6;
    float s = 0.f;
    #pragma unroll
    for (int ks = 0; ks < 32; ks++)
        s += __half2float(g_part16[((size_t)ks * 1024 + d) * 64 + b]);
    float v = tanhf(s);
    g_out[b][d] = v;
    outs[((size_t)b * TT + t) * DD + d] = v;
}

// ---------------- persistent kernel: all 128 timesteps ----------------
__global__ __launch_bounds__(NTHR, 1) void main_kernel(
    float* __restrict__ outs, float* __restrict__ attns) {
    extern __shared__ char dynsm[];
    SmemU* sm = (SmemU*)dynsm;
    __shared__ const float* rp1[64];
    __shared__ const float* rp2[64];
    __shared__ float sc[SS];
    __shared__ float red[8];
    const int tid = threadIdx.x;
    const int bid = blockIdx.x;

    const int rb0 = (bid & 15) * 256, ks0 = (bid >> 4) * 256;  // lstm tiles
    const int rbO = (bid & 3) * 256,  ksO = (bid >> 2) * 64;   // out tiles

    for (int t = 0; t < TT; t++) {
        // lstm0 gates: x = [out | h0], K=2048, 16 rowtiles x 8 ksplit
        if (tid < 64) { rp1[tid] = &g_out[tid][0]; rp2[tid] = &g_h0[tid][0]; }
        __syncthreads();
        gemm_async(rb0, ks0, 256, g_Wf0, 128, rp1, rp2, DD,
                   g_part16 + (size_t)(bid >> 4) * 4096 * 64, &sm->g, 0, 0);
        grid_barrier();
        cell_phase(0, t);
        grid_barrier();
        // lstm1 gates: x = [h0 | h1]
        if (tid < 64) { rp1[tid] = &g_h0[tid][0]; rp2[tid] = &g_h1[tid][0]; }
        __syncthreads();
        gemm_async(rb0, ks0, 256, g_Wf1, 128, rp1, rp2, DD,
                   g_part16 + (size_t)(bid >> 4) * 4096 * 64, &sm->g, 0, 0);
        grid_barrier();
        cell_phase(1, t);
        grid_barrier();
        attn_phase(t, attns, &sm->a, sc, red);
        grid_barrier();
        // out gemm: x = [wctx | h1], 4 rowtiles x 32 ksplit
        if (tid < 64) { rp1[tid] = &g_wctx[tid][0]; rp2[tid] = &g_h1[tid][0]; }
        __syncthreads();
        gemm_async(rbO, ksO, 64, g_WfO, 128, rp1, rp2, DD,
                   g_part16 + (size_t)(bid >> 2) * 1024 * 64, &sm->g, 0, 0);
        grid_barrier();
        outred_phase(t, outs);
        grid_barrier();     // next step's lstm0 reads g_out
    }
}

// ---------------- final ----------------
__global__ void final_kernel(float* __restrict__ hout, float* __restrict__ cout) {
    int i = blockIdx.x * blockDim.x + threadIdx.x;
    if (i < BB * DD) {
        hout[i]           = ((float*)g_h0)[i];
        hout[BB * DD + i] = ((float*)g_h1)[i];
        cout[i]           = ((float*)g_c0)[i];
        cout[BB * DD + i] = ((float*)g_c1)[i];
    }
}

// ---------------- launch ----------------
extern "C" void kernel_launch(void* const* d_in, const int* in_sizes, int n_in,
                              void* d_out, int out_size) {
    const int*   input    = (const int*)d_in[0];
    const float* h0       = (const float*)d_in[2];
    const float* c0       = (const float*)d_in[3];
    const float* context  = (const float*)d_in[4];
    const float* init_out = (const float*)d_in[5];
    const float* word_lut = (const float*)d_in[6];
    const float* Wih0 = (const float*)d_in[7];
    const float* Whh0 = (const float*)d_in[8];
    const float* bih0 = (const float*)d_in[9];
    const float* bhh0 = (const float*)d_in[10];
    const float* Wih1 = (const float*)d_in[11];
    const float* Whh1 = (const float*)d_in[12];
    const float* bih1 = (const float*)d_in[13];
    const float* bhh1 = (const float*)d_in[14];
    const float* Win  = (const float*)d_in[15];
    const float* Wout = (const float*)d_in[16];

    float* out   = (float*)d_out;
    float* outs  = out;                           // [B,T,D]
    float* hout  = out + (size_t)BB * TT * DD;    // [2,B,D]
    float* cout  = hout + 2 * BB * DD;            // [2,B,D]
    float* attns = cout + 2 * BB * DD;            // [B,T,S]

    cudaFuncSetAttribute(main_kernel, cudaFuncAttributeMaxDynamicSharedMemorySize,
                         (int)sizeof(SmemU));
    cudaFuncSetAttribute(pre_emb_kernel, cudaFuncAttributeMaxDynamicSharedMemorySize,
                         (int)sizeof(SmemGemm));
    cudaFuncSetAttribute(cq16_kernel, cudaFuncAttributeMaxDynamicSharedMemorySize,
                         (int)sizeof(SmemGemm));

    init_kernel<<<256, 256>>>(h0, c0, init_out, bih0, bhh0, bih1, bhh1);
    ctx16_kernel<<<32768, 256>>>(context);
    // packs: (W1, ld1, off1, W2, ld2, K1w, K16tot, mbTot, which, trans)
    pack_kernel<<<1024, 256>>>(Wih0, 1536, 0,   Wih0, 1536, 512,  32,  256, 0, 0);
    pack_kernel<<<4096, 256>>>(Wih0, 1536, 512, Whh0, 1024, 1024, 128, 256, 1, 0);
    pack_kernel<<<4096, 256>>>(Wih1, 1024, 0,   Whh1, 1024, 1024, 128, 256, 2, 0);
    pack_kernel<<<1024, 256>>>(Wout, 2048, 0,   Wout, 2048, 2048, 128, 64,  3, 0);
    pack_kernel<<<512, 256>>>(Win,  1024, 0,   Win,  1024, 1024, 64,  64,  4, 1);
    cq16_kernel<<<dim3(4, 128), NTHR, sizeof(SmemGemm)>>>(context);
    pre_emb_kernel<<<dim3(16, 128), NTHR, sizeof(SmemGemm)>>>(input, word_lut);
    main_kernel<<<NCTA, NTHR, sizeof(SmemU)>>>(outs, attns);
    final_kernel<<<256, 256>>>(hout, cout);
}